// round 13
// baseline (speedup 1.0000x reference)
#include <cuda_runtime.h>
#include <cstdint>

#define BB 8192      // batch rows
#define NN 4096      // feature dim
#define CH 64        // rows per chunk
#define NCH 8        // chunks per CTA -> 512 rows per CTA

// Feature-major intermediate: S5[f][b], f = k*64+q, shape (4096, 8192). 128MB.
__device__ float g_S5[(size_t)NN * BB];
// Natural-layout stage-2 output (b, l*64+s). 128MB.
__device__ float g_out2[(size_t)BB * NN];

__device__ __forceinline__ uint32_t f2tf32(float f) {
    uint32_t r;
    asm("cvt.rna.tf32.f32 %0, %1;" : "=r"(r) : "f"(f));
    return r;
}

__device__ __forceinline__ void mma16n8k8(float* d, const uint32_t* a,
                                          uint32_t b0, uint32_t b1) {
    asm volatile(
        "mma.sync.aligned.m16n8k8.row.col.f32.tf32.tf32.f32 "
        "{%0,%1,%2,%3}, {%4,%5,%6,%7}, {%8,%9}, {%0,%1,%2,%3};"
        : "+f"(d[0]), "+f"(d[1]), "+f"(d[2]), "+f"(d[3])
        : "r"(a[0]), "r"(a[1]), "r"(a[2]), "r"(a[3]), "r"(b0), "r"(b1));
}

// ---------------------------------------------------------------------------
// Stage 1 TRANSPOSED (M=q, N=b chunk, K=p), depth-2 register pipeline.
//   S5[(j*64+q)*8192 + b] = sum_p w1[j, q, p] * x[b, j*64+p]
// Chunks of 64 b-rows; LDG(c+2) issued before MMA(c) -> loads always in
// flight. Smem: 2 x 4096 + 4096 words = 48KB. Weights cached in areg.
// ---------------------------------------------------------------------------
__global__ __launch_bounds__(128) void gemm_s1t(const float* __restrict__ A,
                                                const float* __restrict__ W,
                                                float* __restrict__ S5) {
    extern __shared__ __align__(16) uint32_t sm[];
    uint32_t* Ws = sm + 2 * 4096;

    const int tid   = threadIdx.x;
    const int warp  = tid >> 5;
    const int lane  = tid & 31;
    const int g     = lane >> 2;
    const int t     = lane & 3;
    const int j     = blockIdx.y;
    const int mbase = blockIdx.x * (CH * NCH);

    // ---- load W1[j] into smem (swizzled tf32) ----
    {
        const float* Wg = W + (size_t)j * 4096;
#pragma unroll
        for (int i = 0; i < 8; i++) {
            const int g4 = tid + i * 128;
            const int q  = g4 >> 4;
            const int c4 = (g4 & 15) * 4;
            const float4 v = *(const float4*)(Wg + q * 64 + c4);
            uint32_t* d = Ws + q * 64 + (c4 ^ (4 * (q & 7)));
            d[0] = f2tf32(v.x); d[1] = f2tf32(v.y);
            d[2] = f2tf32(v.z); d[3] = f2tf32(v.w);
        }
    }
    __syncthreads();

    // ---- cache weight fragments in registers ----
    const int q0 = warp * 16;
    uint32_t areg[8][4];
    {
        const int sa = 4 * g;
#pragma unroll
        for (int ks = 0; ks < 8; ks++) {
            const int k0 = ks * 8;
            areg[ks][0] = Ws[(q0 + g)     * 64 + ((k0 + t)     ^ sa)];
            areg[ks][1] = Ws[(q0 + g + 8) * 64 + ((k0 + t)     ^ sa)];
            areg[ks][2] = Ws[(q0 + g)     * 64 + ((k0 + t + 4) ^ sa)];
            areg[ks][3] = Ws[(q0 + g + 8) * 64 + ((k0 + t + 4) ^ sa)];
        }
    }

    // per-thread chunk-load coords: 1024 float4 per 64x64 chunk, 8 each
    const int br = (tid + 0) >> 4;          // base row pattern: idx>>4
    // (recomputed inline below to save registers)

    float4 va[8], vb[8];
#pragma unroll
    for (int i = 0; i < 8; i++) {
        const int idx = tid + i * 128;
        va[i] = *(const float4*)(A + (size_t)(mbase + (idx >> 4)) * NN + j * 64 + (idx & 15) * 4);
    }
#pragma unroll
    for (int i = 0; i < 8; i++) {
        const int idx = tid + i * 128;
        vb[i] = *(const float4*)(A + (size_t)(mbase + CH + (idx >> 4)) * NN + j * 64 + (idx & 15) * 4);
    }
    (void)br;

#pragma unroll
    for (int c = 0; c < NCH; c++) {
        uint32_t* cur = sm + (c & 1) * 4096;
        float4*   v   = (c & 1) ? vb : va;

        // ---- STS chunk c (tf32, swizzled) ----
#pragma unroll
        for (int i = 0; i < 8; i++) {
            const int idx  = tid + i * 128;
            const int brow = idx >> 4;
            const int col  = (idx & 15) * 4;
            uint32_t* d = cur + brow * 64 + (col ^ (4 * (brow & 7)));
            d[0] = f2tf32(v[i].x); d[1] = f2tf32(v[i].y);
            d[2] = f2tf32(v[i].z); d[3] = f2tf32(v[i].w);
        }
        // ---- LDG chunk c+2 into the freed register buffer ----
        if (c + 2 < NCH) {
            const int mb = mbase + (c + 2) * CH;
#pragma unroll
            for (int i = 0; i < 8; i++) {
                const int idx = tid + i * 128;
                v[i] = *(const float4*)(A + (size_t)(mb + (idx >> 4)) * NN + j * 64 + (idx & 15) * 4);
            }
        }
        __syncthreads();   // chunk c visible; prior reader of 'cur' done

        // ---- MMA: warp tile 16(q) x 64(b), K=64 ----
        float acc[8][4] = {};
#pragma unroll
        for (int ks = 0; ks < 8; ks++) {
            const int k0 = ks * 8;
            const int sa = 4 * g;
            const uint32_t i0 = (k0 + t) ^ sa;
            const uint32_t i1 = (k0 + t + 4) ^ sa;
#pragma unroll
            for (int ni = 0; ni < 8; ni++) {
                const uint32_t b0 = cur[(ni * 8 + g) * 64 + i0];
                const uint32_t b1 = cur[(ni * 8 + g) * 64 + i1];
                mma16n8k8(acc[ni], areg[ks], b0, b1);
            }
        }

        // ---- direct feature-major STG ----
        const int mb = mbase + c * CH;
        float* R0 = S5 + (size_t)(j * 64 + q0 + g)     * BB + mb + 2 * t;
        float* R1 = S5 + (size_t)(j * 64 + q0 + g + 8) * BB + mb + 2 * t;
#pragma unroll
        for (int ni = 0; ni < 8; ni++) {
            *(float2*)(R0 + ni * 8) = make_float2(acc[ni][0], acc[ni][1]);
            *(float2*)(R1 + ni * 8) = make_float2(acc[ni][2], acc[ni][3]);
        }
    }
}

// ---------------------------------------------------------------------------
// Stage 2: feature-major read (permutation free), depth-2 register pipeline,
// natural write.   out2[b, l*64+s] = sum_r S5[(r*64+l)*8192 + b] * w2[l,s,r]
// Chunks of 64 b-rows; A-chunk K-major As[r*68 + b'] (17KB x2) + W 16KB.
// ---------------------------------------------------------------------------
__global__ __launch_bounds__(128) void gemm_s2(const float* __restrict__ S5,
                                               const float* __restrict__ W,
                                               float* __restrict__ C) {
    extern __shared__ __align__(16) uint32_t sm[];
    uint32_t* Ws = sm + 2 * 4352;

    const int tid   = threadIdx.x;
    const int warp  = tid >> 5;
    const int lane  = tid & 31;
    const int g     = lane >> 2;
    const int t     = lane & 3;
    const int j     = blockIdx.y;                 // l block
    const int mbase = blockIdx.x * (CH * NCH);

    // ---- load w2[l] into smem (swizzled tf32) ----
    {
        const float* Wg = W + (size_t)j * 4096;
#pragma unroll
        for (int i = 0; i < 8; i++) {
            const int g4 = tid + i * 128;
            const int s  = g4 >> 4;
            const int c4 = (g4 & 15) * 4;
            const float4 v = *(const float4*)(Wg + s * 64 + c4);
            uint32_t* d = Ws + s * 64 + (c4 ^ (4 * (s & 7)));
            d[0] = f2tf32(v.x); d[1] = f2tf32(v.y);
            d[2] = f2tf32(v.z); d[3] = f2tf32(v.w);
        }
    }

    float4 va[8], vb[8];
#pragma unroll
    for (int i = 0; i < 8; i++) {
        const int idx = tid + i * 128;
        va[i] = *(const float4*)(S5 + (size_t)((idx >> 4) * 64 + j) * BB + mbase + (idx & 15) * 4);
    }
#pragma unroll
    for (int i = 0; i < 8; i++) {
        const int idx = tid + i * 128;
        vb[i] = *(const float4*)(S5 + (size_t)((idx >> 4) * 64 + j) * BB + mbase + CH + (idx & 15) * 4);
    }

#pragma unroll
    for (int c = 0; c < NCH; c++) {
        uint32_t* cur = sm + (c & 1) * 4352;
        float4*   v   = (c & 1) ? vb : va;

        // ---- STS chunk c: K-major As[r*68 + b'] ----
#pragma unroll
        for (int i = 0; i < 8; i++) {
            const int idx = tid + i * 128;
            uint32_t* d = cur + (idx >> 4) * 68 + (idx & 15) * 4;
            d[0] = f2tf32(v[i].x); d[1] = f2tf32(v[i].y);
            d[2] = f2tf32(v[i].z); d[3] = f2tf32(v[i].w);
        }
        // ---- LDG chunk c+2 ----
        if (c + 2 < NCH) {
            const int mb = mbase + (c + 2) * CH;
#pragma unroll
            for (int i = 0; i < 8; i++) {
                const int idx = tid + i * 128;
                v[i] = *(const float4*)(S5 + (size_t)((idx >> 4) * 64 + j) * BB + mb + (idx & 15) * 4);
            }
        }
        __syncthreads();

        // ---- MMA: warp tile 16(b) x 64(s), K=64 ----
        const int b0r = warp * 16;
        float acc[8][4] = {};
#pragma unroll
        for (int ks = 0; ks < 8; ks++) {
            const int k0 = ks * 8;
            uint32_t a[4];
            a[0] = cur[(k0 + t)     * 68 + b0r + g];
            a[1] = cur[(k0 + t)     * 68 + b0r + g + 8];
            a[2] = cur[(k0 + t + 4) * 68 + b0r + g];
            a[3] = cur[(k0 + t + 4) * 68 + b0r + g + 8];
            const int sa = 4 * g;
#pragma unroll
            for (int ni = 0; ni < 8; ni++) {
                const uint32_t b0 = Ws[(ni * 8 + g) * 64 + ((k0 + t)     ^ sa)];
                const uint32_t b1 = Ws[(ni * 8 + g) * 64 + ((k0 + t + 4) ^ sa)];
                mma16n8k8(acc[ni], a, b0, b1);
            }
        }

        // ---- natural STG (sector-exact float2) ----
        float* Cg = C + (size_t)(mbase + c * CH + b0r) * NN + j * 64;
#pragma unroll
        for (int ni = 0; ni < 8; ni++) {
            const int col = ni * 8 + t * 2;
            *(float2*)(Cg + (size_t)(g)     * NN + col) =
                make_float2(acc[ni][0], acc[ni][1]);
            *(float2*)(Cg + (size_t)(g + 8) * NN + col) =
                make_float2(acc[ni][2], acc[ni][3]);
        }
    }
}

// ---------------------------------------------------------------------------
// Final permutation: out[b, s*64 + l] = in[b, l*64 + s].
// ---------------------------------------------------------------------------
__global__ __launch_bounds__(256) void trans64(const float* __restrict__ in,
                                               float* __restrict__ out) {
    __shared__ float smt[64][65];
    const int b   = blockIdx.x;
    const int tid = threadIdx.x;
    const float* ip = in  + (size_t)b * NN;
    float*       op = out + (size_t)b * NN;

#pragma unroll
    for (int i = 0; i < 16; i++) {
        const int t = tid + i * 256;
        smt[t & 63][t >> 6] = ip[t];
    }
    __syncthreads();
#pragma unroll
    for (int i = 0; i < 16; i++) {
        const int t = tid + i * 256;
        op[t] = smt[t >> 6][t & 63];
    }
}

extern "C" void kernel_launch(void* const* d_in, const int* in_sizes, int n_in,
                              void* d_out, int out_size) {
    const float* x  = (const float*)d_in[0];   // (8192, 4096)
    const float* w1 = (const float*)d_in[1];   // (64, 64, 64)
    const float* w2 = (const float*)d_in[2];   // (64, 64, 64)
    float* out = (float*)d_out;

    float *S5 = nullptr, *out2 = nullptr;
    cudaGetSymbolAddress((void**)&S5, g_S5);
    cudaGetSymbolAddress((void**)&out2, g_out2);

    const int smem1 = (2 * 4096 + 4096) * 4;   // 49152
    const int smem2 = (2 * 4352 + 4096) * 4;   // 51200
    cudaFuncSetAttribute(gemm_s1t, cudaFuncAttributeMaxDynamicSharedMemorySize, smem1);
    cudaFuncSetAttribute(gemm_s2,  cudaFuncAttributeMaxDynamicSharedMemorySize, smem2);

    dim3 ggrid(BB / (CH * NCH), 64);   // (16, 64)

    // Stage 1 (transposed): x -> S5 (feature-major). Mid-permutation absorbed.
    gemm_s1t<<<ggrid, 128, smem1>>>(x, w1, S5);
    // Stage 2: S5 (feature-major read) -> out2 (natural (b, l*64+s)).
    gemm_s2<<<ggrid, 128, smem2>>>(S5, w2, out2);
    // Final permutation: out[b, s*64+l] = out2[b, l*64+s].
    trans64<<<BB, 256>>>(out2, out);
}

// round 14
// speedup vs baseline: 1.2458x; 1.2458x over previous
#include <cuda_runtime.h>
#include <cstdint>

#define BB 8192      // batch rows
#define NN 4096      // feature dim
#define TPC 4        // 128-row tiles per CTA

// Feature-major intermediate: S5[f][b], f = k*64+q, shape (4096, 8192). 128MB.
__device__ float g_S5[(size_t)NN * BB];
// Natural-layout stage-2 output (b, l*64+s). 128MB.
__device__ float g_out2[(size_t)BB * NN];

__device__ __forceinline__ uint32_t f2tf32(float f) {
    uint32_t r;
    asm("cvt.rna.tf32.f32 %0, %1;" : "=r"(r) : "f"(f));
    return r;
}
__device__ __forceinline__ uint32_t b2tf32(uint32_t bits) {
    uint32_t r;
    asm("cvt.rna.tf32.f32 %0, %1;" : "=r"(r) : "f"(__uint_as_float(bits)));
    return r;
}
__device__ __forceinline__ void cp16(uint32_t dst_smem, const void* src) {
    asm volatile("cp.async.cg.shared.global [%0], [%1], 16;"
                 :: "r"(dst_smem), "l"(src));
}
__device__ __forceinline__ void cp_commit() {
    asm volatile("cp.async.commit_group;");
}
template <int N>
__device__ __forceinline__ void cp_wait() {
    asm volatile("cp.async.wait_group %0;" :: "n"(N));
}

__device__ __forceinline__ void mma16n8k8(float* d, const uint32_t* a,
                                          uint32_t b0, uint32_t b1) {
    asm volatile(
        "mma.sync.aligned.m16n8k8.row.col.f32.tf32.tf32.f32 "
        "{%0,%1,%2,%3}, {%4,%5,%6,%7}, {%8,%9}, {%0,%1,%2,%3};"
        : "+f"(d[0]), "+f"(d[1]), "+f"(d[2]), "+f"(d[3])
        : "r"(a[0]), "r"(a[1]), "r"(a[2]), "r"(a[3]), "r"(b0), "r"(b1));
}

// ---------------------------------------------------------------------------
// Stage 1 TRANSPOSED (M=q, N=b, K=p), cp.async double-buffered pipeline.
//   S5[(j*64+q)*8192 + b] = sum_p w1[j, q, p] * x[b, j*64+p]
// Weights -> registers straight from global (no W smem). X tiles arrive raw
// fp32 via cp.async into swizzled smem; fragments RNA-converted in-register.
// Smem: 2 x 8192 words (64KB) -> 3 CTA/SM.
// ---------------------------------------------------------------------------
__global__ __launch_bounds__(128, 3) void gemm_s1t(const float* __restrict__ A,
                                                   const float* __restrict__ W,
                                                   float* __restrict__ S5) {
    extern __shared__ __align__(16) uint32_t sm[];

    const int tid   = threadIdx.x;
    const int warp  = tid >> 5;
    const int lane  = tid & 31;
    const int g     = lane >> 2;
    const int t     = lane & 3;
    const int j     = blockIdx.y;
    const int mbase = blockIdx.x * (128 * TPC);

    const uint32_t smb = (uint32_t)__cvta_generic_to_shared(sm);

    // ---- weight fragments straight from global (RNA tf32) ----
    const int q0 = warp * 16;
    uint32_t areg[8][4];
    {
        const float* Wg = W + (size_t)j * 4096;
#pragma unroll
        for (int ks = 0; ks < 8; ks++) {
            const int k0 = ks * 8;
            areg[ks][0] = f2tf32(Wg[(q0 + g)     * 64 + k0 + t]);
            areg[ks][1] = f2tf32(Wg[(q0 + g + 8) * 64 + k0 + t]);
            areg[ks][2] = f2tf32(Wg[(q0 + g)     * 64 + k0 + t + 4]);
            areg[ks][3] = f2tf32(Wg[(q0 + g + 8) * 64 + k0 + t + 4]);
        }
    }

    // ---- cp.async issue helper data: 16 float4-chunks per thread per tile ----
    // chunk idx: row = idx>>4 (0..127), col = (idx&15)*4
    // smem word: row*64 + (col ^ 4*(row&7))   (16B-aligned: swizzle flips bits>=2)

    // preamble: issue tile 0 -> buf0
    {
        const float* Ag = A + (size_t)mbase * NN + j * 64;
#pragma unroll
        for (int i = 0; i < 16; i++) {
            const int idx = tid + i * 128;
            const int row = idx >> 4;
            const int col = (idx & 15) * 4;
            cp16(smb + (row * 64 + (col ^ (4 * (row & 7)))) * 4,
                 Ag + (size_t)row * NN + col);
        }
        cp_commit();
    }

#pragma unroll
    for (int c = 0; c < TPC; c++) {
        uint32_t* cur = sm + (c & 1) * 8192;

        // issue tile c+1 into the other buffer
        if (c + 1 < TPC) {
            const uint32_t dstb = smb + ((c + 1) & 1) * 8192 * 4;
            const float* Ag = A + (size_t)(mbase + (c + 1) * 128) * NN + j * 64;
#pragma unroll
            for (int i = 0; i < 16; i++) {
                const int idx = tid + i * 128;
                const int row = idx >> 4;
                const int col = (idx & 15) * 4;
                cp16(dstb + (row * 64 + (col ^ (4 * (row & 7)))) * 4,
                     Ag + (size_t)row * NN + col);
            }
            cp_commit();
            cp_wait<1>();
        } else {
            cp_wait<0>();
        }
        __syncthreads();   // tile c complete CTA-wide

        // ---- MMA: warp tile 16(q) x 128(b); B-frags cvt'd in-register ----
        float acc[16][4] = {};
#pragma unroll
        for (int ks = 0; ks < 8; ks++) {
            const int k0 = ks * 8;
            const int sa = 4 * g;
            const uint32_t i0 = (k0 + t) ^ sa;
            const uint32_t i1 = (k0 + t + 4) ^ sa;
#pragma unroll
            for (int ni = 0; ni < 16; ni++) {
                const uint32_t b0 = b2tf32(cur[(ni * 8 + g) * 64 + i0]);
                const uint32_t b1 = b2tf32(cur[(ni * 8 + g) * 64 + i1]);
                mma16n8k8(acc[ni], areg[ks], b0, b1);
            }
        }
        __syncthreads();   // done reading cur before tile c+2 overwrites it

        // ---- direct feature-major STG (sector-exact float2) ----
        const int mb = mbase + c * 128;
        float* R0 = S5 + (size_t)(j * 64 + q0 + g)     * BB + mb + 2 * t;
        float* R1 = S5 + (size_t)(j * 64 + q0 + g + 8) * BB + mb + 2 * t;
#pragma unroll
        for (int ni = 0; ni < 16; ni++) {
            *(float2*)(R0 + ni * 8) = make_float2(acc[ni][0], acc[ni][1]);
            *(float2*)(R1 + ni * 8) = make_float2(acc[ni][2], acc[ni][3]);
        }
    }
}

// ---------------------------------------------------------------------------
// Stage 2: feature-major read via cp.async (permutation free), natural write.
//   out2[b, l*64+s] = sum_r S5[(r*64+l)*8192 + b] * w2[l, s, r]
// A tiles raw fp32 K-major As[r*136 + b'] (34KB x2), W smem tf32 16KB.
// A-fragments RNA-converted in-register. 84KB smem -> 2 CTA/SM.
// ---------------------------------------------------------------------------
#define S2ABW 8704   // 136 * 64 words per buffer

__global__ __launch_bounds__(128, 2) void gemm_s2(const float* __restrict__ S5,
                                                  const float* __restrict__ W,
                                                  float* __restrict__ C) {
    extern __shared__ __align__(16) uint32_t sm[];
    uint32_t* Ws = sm + 2 * S2ABW;

    const int tid   = threadIdx.x;
    const int warp  = tid >> 5;
    const int lane  = tid & 31;
    const int g     = lane >> 2;
    const int t     = lane & 3;
    const int j     = blockIdx.y;                 // l block
    const int mbase = blockIdx.x * (128 * TPC);

    const uint32_t smb = (uint32_t)__cvta_generic_to_shared(sm);

    // ---- load w2[l] into smem (tf32, swizzled) ----
    {
        const float* Wg = W + (size_t)j * 4096;
#pragma unroll
        for (int i = 0; i < 8; i++) {
            const int g4 = tid + i * 128;
            const int s  = g4 >> 4;
            const int c4 = (g4 & 15) * 4;
            const float4 v = *(const float4*)(Wg + s * 64 + c4);
            uint32_t* d = Ws + s * 64 + (c4 ^ (4 * (s & 7)));
            d[0] = f2tf32(v.x); d[1] = f2tf32(v.y);
            d[2] = f2tf32(v.z); d[3] = f2tf32(v.w);
        }
    }

    // chunk idx: r = idx>>5 (0..63), bcol = (idx&31)*4 (0..124)
    // smem word: r*136 + bcol  (544B row pitch: 16B-aligned)

    // preamble: issue tile 0
    {
#pragma unroll
        for (int i = 0; i < 16; i++) {
            const int idx = tid + i * 128;
            const int r   = idx >> 5;
            const int bc  = (idx & 31) * 4;
            cp16(smb + (r * 136 + bc) * 4,
                 S5 + (size_t)(r * 64 + j) * BB + mbase + bc);
        }
        cp_commit();
    }

    const int rb0 = warp * 32;

#pragma unroll
    for (int c = 0; c < TPC; c++) {
        uint32_t* cur = sm + (c & 1) * S2ABW;

        if (c + 1 < TPC) {
            const uint32_t dstb = smb + ((c + 1) & 1) * S2ABW * 4;
            const int mb = mbase + (c + 1) * 128;
#pragma unroll
            for (int i = 0; i < 16; i++) {
                const int idx = tid + i * 128;
                const int r   = idx >> 5;
                const int bc  = (idx & 31) * 4;
                cp16(dstb + (r * 136 + bc) * 4,
                     S5 + (size_t)(r * 64 + j) * BB + mb + bc);
            }
            cp_commit();
            cp_wait<1>();
        } else {
            cp_wait<0>();
        }
        __syncthreads();

        // ---- MMA: warp tile 32(b) x 64(s); A-frags cvt'd in-register ----
        float acc[2][8][4] = {};
#pragma unroll
        for (int ks = 0; ks < 8; ks++) {
            const int k0 = ks * 8;
            uint32_t a[2][4];
#pragma unroll
            for (int mi = 0; mi < 2; mi++) {
                const int rb = rb0 + mi * 16;
                a[mi][0] = b2tf32(cur[(k0 + t)     * 136 + rb + g]);
                a[mi][1] = b2tf32(cur[(k0 + t)     * 136 + rb + g + 8]);
                a[mi][2] = b2tf32(cur[(k0 + t + 4) * 136 + rb + g]);
                a[mi][3] = b2tf32(cur[(k0 + t + 4) * 136 + rb + g + 8]);
            }
            const int sa = 4 * g;
#pragma unroll
            for (int ni = 0; ni < 8; ni++) {
                const uint32_t b0 = Ws[(ni * 8 + g) * 64 + ((k0 + t)     ^ sa)];
                const uint32_t b1 = Ws[(ni * 8 + g) * 64 + ((k0 + t + 4) ^ sa)];
                mma16n8k8(acc[0][ni], a[0], b0, b1);
                mma16n8k8(acc[1][ni], a[1], b0, b1);
            }
        }
        __syncthreads();   // done reading cur before tile c+2 overwrites

        // ---- natural STG (sector-exact float2) ----
        float* Cg = C + (size_t)(mbase + c * 128) * NN + j * 64;
#pragma unroll
        for (int mi = 0; mi < 2; mi++) {
            const int r0 = rb0 + mi * 16 + g;
#pragma unroll
            for (int ni = 0; ni < 8; ni++) {
                const int col = ni * 8 + t * 2;
                *(float2*)(Cg + (size_t)r0 * NN + col) =
                    make_float2(acc[mi][ni][0], acc[mi][ni][1]);
                *(float2*)(Cg + (size_t)(r0 + 8) * NN + col) =
                    make_float2(acc[mi][ni][2], acc[mi][ni][3]);
            }
        }
    }
}

// ---------------------------------------------------------------------------
// Final permutation: out[b, s*64 + l] = in[b, l*64 + s].
// ---------------------------------------------------------------------------
__global__ __launch_bounds__(256) void trans64(const float* __restrict__ in,
                                               float* __restrict__ out) {
    __shared__ float smt[64][65];
    const int b   = blockIdx.x;
    const int tid = threadIdx.x;
    const float* ip = in  + (size_t)b * NN;
    float*       op = out + (size_t)b * NN;

#pragma unroll
    for (int i = 0; i < 16; i++) {
        const int t = tid + i * 256;
        smt[t & 63][t >> 6] = ip[t];
    }
    __syncthreads();
#pragma unroll
    for (int i = 0; i < 16; i++) {
        const int t = tid + i * 256;
        op[t] = smt[t >> 6][t & 63];
    }
}

extern "C" void kernel_launch(void* const* d_in, const int* in_sizes, int n_in,
                              void* d_out, int out_size) {
    const float* x  = (const float*)d_in[0];   // (8192, 4096)
    const float* w1 = (const float*)d_in[1];   // (64, 64, 64)
    const float* w2 = (const float*)d_in[2];   // (64, 64, 64)
    float* out = (float*)d_out;

    float *S5 = nullptr, *out2 = nullptr;
    cudaGetSymbolAddress((void**)&S5, g_S5);
    cudaGetSymbolAddress((void**)&out2, g_out2);

    const int smem1 = 2 * 8192 * 4;                 // 65536
    const int smem2 = (2 * S2ABW + 4096) * 4;       // 86016
    cudaFuncSetAttribute(gemm_s1t, cudaFuncAttributeMaxDynamicSharedMemorySize, smem1);
    cudaFuncSetAttribute(gemm_s2,  cudaFuncAttributeMaxDynamicSharedMemorySize, smem2);

    dim3 ggrid(BB / (128 * TPC), 64);   // (16, 64)

    // Stage 1 (transposed): x -> S5 (feature-major). Mid-permutation absorbed.
    gemm_s1t<<<ggrid, 128, smem1>>>(x, w1, S5);
    // Stage 2: S5 (feature-major read) -> out2 (natural (b, l*64+s)).
    gemm_s2<<<ggrid, 128, smem2>>>(S5, w2, out2);
    // Final permutation: out[b, s*64+l] = out2[b, l*64+s].
    trans64<<<BB, 256>>>(out2, out);
}